// round 9
// baseline (speedup 1.0000x reference)
#include <cuda_runtime.h>
#include <cstdint>

// ---------------------------------------------------------------------------
// SpikingOpticalFlowBranch — fused flow-diff + conv3x3(2->64) + LIF scan.
// R9: 4-way channel split (16 ch/thread, grid 4096, launch_bounds(256,4))
// -> occ 4, n_conc 592, 7 waves with 1.1% tail idle (vs 7.7% at R8) and
// 8 warps/SMSP latency hiding. Epilogue parallelized: K1 grid 20 (logits +
// spike-rate), K2 grid 1 (readout + chsum re-zero for next graph replay).
// Per-channel FMA order identical to R8 -> bit-identical rel_err.
// Output layout: [0,160) readout, [160,3200) logits (t-major), [3200] sr.
// ---------------------------------------------------------------------------

#define T_STEPS 19
#define BATCH   16
#define HH      128
#define WW      128
#define NCH     64
#define QCH     16          // channels per CTA (quarter)
#define OUTD    10
#define BETA_F  0.9f
#define THR_F   1.0f
#define HALO    18
#define FRAME_ELEMS (HALO*HALO*2)   // 648

__device__ int g_chsum[T_STEPS * BATCH * NCH];   // static-init 0; K2 re-zeros

// ---------------------------------------------------------------------------
// Main kernel: grid = 16 batch x 64 tiles x 4 channel-quarters = 4096 blocks,
// 256 threads. Thread = one pixel, 16 channels of V in registers, 19 steps.
// ---------------------------------------------------------------------------
__global__ __launch_bounds__(256, 4)
void lif_main_kernel(const float* __restrict__ x,
                     const float* __restrict__ wconv,
                     const float* __restrict__ bconv) {
    __shared__ float  frame_s[2][FRAME_ELEMS];   // ping-pong raw frames
    __shared__ float  flow_s[FRAME_ELEMS];       // current flow tile
    __shared__ float4 ws4[18 * 4];               // weights [tap][4 x float4] (16 ch)
    __shared__ float4 bs4[4];                    // bias (this quarter)
    __shared__ int    chsum_s[QCH];

    const int tid  = threadIdx.x;
    const int lane = tid & 31;
    const int q    = blockIdx.x & 3;             // channel quarter
    const int tile = (blockIdx.x >> 2) & 63;
    const int b    = blockIdx.x >> 8;            // batch
    const int th0  = (tile >> 3) << 4;
    const int tw0  = (tile & 7) << 4;
    const int ty   = tid >> 4;
    const int tx   = tid & 15;

    // weights: global [ky][kx][ci][co] == [tap 0..17][co 0..63]; take our 16 co
    {
        float* wsf = reinterpret_cast<float*>(ws4);
        for (int i = tid; i < 18 * QCH; i += 256) {
            int tap = i >> 4, c = i & 15;
            wsf[i] = wconv[tap * NCH + q * QCH + c];
        }
        if (tid < QCH) reinterpret_cast<float*>(bs4)[tid] = bconv[q * QCH + tid];
    }

    auto load_frame = [&](int t, float* dst) {
        const float* xt = x + ((size_t)t * BATCH + b) * (HH * WW * 2);
        for (int i = tid; i < FRAME_ELEMS; i += 256) {
            int row = i / (HALO * 2);
            int rem = i - row * (HALO * 2);
            int col = rem >> 1;
            int c   = rem & 1;
            int gh  = th0 + row - 1;
            int gw  = tw0 + col - 1;
            float v = 0.0f;
            if ((unsigned)gh < (unsigned)HH && (unsigned)gw < (unsigned)WW)
                v = xt[(gh * WW + gw) * 2 + c];
            dst[i] = v;
        }
    };

    load_frame(0, frame_s[0]);

    float V[QCH];
#pragma unroll
    for (int ch = 0; ch < QCH; ch++) V[ch] = 0.0f;

#pragma unroll 1
    for (int t = 0; t < T_STEPS; t++) {
        // stage next frame + zero per-block counters
        if (tid < QCH) chsum_s[tid] = 0;
        load_frame(t + 1, frame_s[(t + 1) & 1]);
        __syncthreads();

        {   // flow tile = frame[t+1] - frame[t]
            const float* fc = frame_s[(t + 1) & 1];
            const float* fp = frame_s[t & 1];
            for (int i = tid; i < FRAME_ELEMS; i += 256) flow_s[i] = fc[i] - fp[i];
        }
        __syncthreads();

        // gather 18 taps for this pixel
        float f[18];
#pragma unroll
        for (int dy = 0; dy < 3; dy++)
#pragma unroll
            for (int dx = 0; dx < 3; dx++) {
                int base = ((ty + dy) * HALO + (tx + dx)) * 2;
                f[(dy * 3 + dx) * 2 + 0] = flow_s[base + 0];
                f[(dy * 3 + dx) * 2 + 1] = flow_s[base + 1];
            }

        // V = beta*V + bias   (same per-channel order as R8 -> bit-identical)
#pragma unroll
        for (int c4 = 0; c4 < 4; c4++) {
            float4 bb = bs4[c4];
            V[c4 * 4 + 0] = BETA_F * V[c4 * 4 + 0] + bb.x;
            V[c4 * 4 + 1] = BETA_F * V[c4 * 4 + 1] + bb.y;
            V[c4 * 4 + 2] = BETA_F * V[c4 * 4 + 2] + bb.z;
            V[c4 * 4 + 3] = BETA_F * V[c4 * 4 + 3] + bb.w;
        }
        // V += sum_taps f[tap] * w[tap][ch]
#pragma unroll
        for (int tap = 0; tap < 18; tap++) {
            float fv = f[tap];
#pragma unroll
            for (int c4 = 0; c4 < 4; c4++) {
                float4 w = ws4[tap * 4 + c4];
                V[c4 * 4 + 0] += fv * w.x;
                V[c4 * 4 + 1] += fv * w.y;
                V[c4 * 4 + 2] += fv * w.z;
                V[c4 * 4 + 3] += fv * w.w;
            }
        }

        // spike + soft reset + warp-ballot counting (lane L owns channel L<16)
        int acc = 0;
#pragma unroll
        for (int ch = 0; ch < QCH; ch++) {
            bool s = V[ch] > THR_F;
            unsigned m = __ballot_sync(0xffffffffu, s);
            if (s) V[ch] -= THR_F;
            if (lane == ch) acc += __popc(m);
        }
        if (lane < QCH) atomicAdd(&chsum_s[lane], acc);
        __syncthreads();

        if (tid < QCH)
            atomicAdd(&g_chsum[(t * BATCH + b) * NCH + q * QCH + tid], chsum_s[tid]);
    }
}

// ---------------------------------------------------------------------------
// Epilogue K1: grid 20. Blocks 0..18: logits for time t. Block 19: spike-rate.
// ---------------------------------------------------------------------------
__global__ void epilogue1_kernel(const float* __restrict__ w_head,
                                 const float* __restrict__ b_head,
                                 float* __restrict__ out) {
    const int t = blockIdx.x;
    const int tid = threadIdx.x;

    if (t < T_STEPS) {
        // 160 threads: (b,o); logits[t][b][o] = sum_ch (cnt/2^14) * w + bias
        if (tid < BATCH * OUTD) {
            int b = tid / OUTD, o = tid % OUTD;
            const int* cs = g_chsum + (t * BATCH + b) * NCH;
            float acc = b_head[o];
            for (int ch = 0; ch < NCH; ch++)
                acc += ((float)cs[ch] * (1.0f / 16384.0f)) * w_head[ch * OUTD + o];
            out[160 + (t * BATCH + b) * OUTD + o] = acc;
        }
    } else {
        // block 19: sr = total spikes / (19*16*128*128*64)
        __shared__ long long part[256];
        long long tot = 0;
        for (int i = tid; i < T_STEPS * BATCH * NCH; i += 256)
            tot += (long long)g_chsum[i];
        part[tid] = tot;
        __syncthreads();
        for (int s = 128; s > 0; s >>= 1) {
            if (tid < s) part[tid] += part[tid + s];
            __syncthreads();
        }
        if (tid == 0)
            out[3200] = (float)((double)part[0] / 318767104.0);
    }
}

// ---------------------------------------------------------------------------
// Epilogue K2: readout = mean_t logits; re-zero g_chsum for next replay.
// ---------------------------------------------------------------------------
__global__ void epilogue2_kernel(float* __restrict__ out) {
    const int tid = threadIdx.x;
    if (tid < BATCH * OUTD) {
        int b = tid / OUTD, o = tid % OUTD;
        float s = 0.0f;
        for (int t = 0; t < T_STEPS; t++)
            s += out[160 + (t * BATCH + b) * OUTD + o];
        out[b * OUTD + o] = s * (1.0f / (float)T_STEPS);
    }
    for (int i = tid; i < T_STEPS * BATCH * NCH; i += 256) g_chsum[i] = 0;
}

// ---------------------------------------------------------------------------
extern "C" void kernel_launch(void* const* d_in, const int* in_sizes, int n_in,
                              void* d_out, int out_size) {
    const float* x     = (const float*)d_in[0];   // [20,16,128,128,2]
    const float* wconv = (const float*)d_in[1];   // [3,3,2,64]
    const float* bconv = (const float*)d_in[2];   // [64]
    const float* whead = (const float*)d_in[3];   // [64,10]
    const float* bhead = (const float*)d_in[4];   // [10]
    float* out = (float*)d_out;                   // 3201 floats

    lif_main_kernel<<<BATCH * 64 * 4, 256>>>(x, wconv, bconv);
    epilogue1_kernel<<<20, 256>>>(whead, bhead, out);
    epilogue2_kernel<<<1, 256>>>(out);
}

// round 10
// speedup vs baseline: 1.4369x; 1.4369x over previous
#include <cuda_runtime.h>
#include <cstdint>

// ---------------------------------------------------------------------------
// SpikingOpticalFlowBranch — fused flow-diff + conv3x3(2->64) + LIF scan.
// R10: evidence-driven (R9 ncu: alu 36% > fma 32%, L1 79% => issue-bound on
// non-FMA work). Thread = 2 vertical pixels x 16 channels: weight LDS.128
// amortized over 8 FMAs; frame-loader index math hoisted out of the t-loop;
// flow phase removed (taps = frame_next - frame_prev at use). Conv tap order
// unchanged (ky,kx,ci ascending) -> bit-identical numerics.
// Output layout: [0,160) readout, [160,3200) logits (t-major), [3200] sr.
// ---------------------------------------------------------------------------

#define T_STEPS 19
#define BATCH   16
#define HH      128
#define WW      128
#define NCH     64
#define QCH     16          // channels per CTA
#define OUTD    10
#define BETA_F  0.9f
#define THR_F   1.0f

#define TILE_R  32          // tile rows per CTA
#define TILE_C  16          // tile cols per CTA
#define HALO_R  34
#define HALO_C  18
#define FRAME_ELEMS (HALO_R*HALO_C*2)   // 1224 floats
#define LOAD_ITERS 5                     // ceil(1224/256)

__device__ int g_chsum[T_STEPS * BATCH * NCH];   // static-init 0; epilogue2 re-zeros

// ---------------------------------------------------------------------------
// Main kernel: grid = 16 batch x 32 tiles x 4 channel-quarters = 2048 blocks,
// 256 threads. Thread = 2 pixels (rows 2*typ, 2*typ+1) x 16 channels.
// ---------------------------------------------------------------------------
__global__ __launch_bounds__(256, 3)
void lif_main_kernel(const float* __restrict__ x,
                     const float* __restrict__ wconv,
                     const float* __restrict__ bconv) {
    __shared__ float  frame_s[2][FRAME_ELEMS];   // ping-pong raw frames (halo'd)
    __shared__ float4 ws4[18 * 4];               // weights [tap][4 x float4] (16 ch)
    __shared__ float4 bs4[4];                    // bias (this quarter)
    __shared__ int    chsum_s[QCH];

    const int tid  = threadIdx.x;
    const int lane = tid & 31;
    const int q    = blockIdx.x & 3;             // channel quarter
    const int tile = (blockIdx.x >> 2) & 31;     // 4 row-tiles x 8 col-tiles
    const int b    = blockIdx.x >> 7;            // batch
    const int th0  = (tile >> 3) * TILE_R;
    const int tw0  = (tile & 7) * TILE_C;
    const int tx   = tid & 15;                   // col in tile
    const int typ  = tid >> 4;                   // pixel-pair row (0..15)
    const int r0   = typ * 2;                    // first of the 2 rows

    // weights: global [ky][kx][ci][co] == [tap 0..17][co 0..63]; take our 16 co
    {
        float* wsf = reinterpret_cast<float*>(ws4);
        for (int i = tid; i < 18 * QCH; i += 256) {
            int tap = i >> 4, c = i & 15;
            wsf[i] = wconv[tap * NCH + q * QCH + c];
        }
        if (tid < QCH) reinterpret_cast<float*>(bs4)[tid] = bconv[q * QCH + tid];
        if (tid < QCH) chsum_s[tid] = 0;
    }

    // ---- hoisted loader state: indices are t-invariant ----
    int  gofs[LOAD_ITERS];
    bool gval[LOAD_ITERS];
#pragma unroll
    for (int k = 0; k < LOAD_ITERS; k++) {
        int i = tid + k * 256;
        gval[k] = false;
        gofs[k] = 0;
        if (i < FRAME_ELEMS) {
            int row = i / (HALO_C * 2);
            int rem = i - row * (HALO_C * 2);
            int col = rem >> 1;
            int c   = rem & 1;
            int gh  = th0 + row - 1;
            int gw  = tw0 + col - 1;
            if ((unsigned)gh < (unsigned)HH && (unsigned)gw < (unsigned)WW) {
                gval[k] = true;
                gofs[k] = (gh * WW + gw) * 2 + c;
            }
        }
    }

    auto load_frame = [&](int t, float* dst) {
        const float* xt = x + ((size_t)t * BATCH + b) * (HH * WW * 2);
#pragma unroll
        for (int k = 0; k < LOAD_ITERS; k++) {
            int i = tid + k * 256;
            if (i < FRAME_ELEMS) dst[i] = gval[k] ? __ldg(xt + gofs[k]) : 0.0f;
        }
    };

    load_frame(0, frame_s[0]);

    float V0[QCH], V1[QCH];
#pragma unroll
    for (int ch = 0; ch < QCH; ch++) { V0[ch] = 0.0f; V1[ch] = 0.0f; }

#pragma unroll 1
    for (int t = 0; t < T_STEPS; t++) {
        __syncthreads();                        // prev taps + chsum adds done
        load_frame(t + 1, frame_s[(t + 1) & 1]);
        if (t > 0 && tid < QCH) {               // flush t-1 counts, re-zero
            atomicAdd(&g_chsum[((t - 1) * BATCH + b) * NCH + q * QCH + tid],
                      chsum_s[tid]);
            chsum_s[tid] = 0;
        }
        __syncthreads();                        // frame t+1 ready

        const float2* n2 = reinterpret_cast<const float2*>(frame_s[(t + 1) & 1]);
        const float2* p2 = reinterpret_cast<const float2*>(frame_s[t & 1]);

        // V = beta*V + bias  (per-channel order identical to R5/R8)
#pragma unroll
        for (int j = 0; j < 4; j++) {
            float4 bb = bs4[j];
            V0[4*j+0] = BETA_F * V0[4*j+0] + bb.x;  V1[4*j+0] = BETA_F * V1[4*j+0] + bb.x;
            V0[4*j+1] = BETA_F * V0[4*j+1] + bb.y;  V1[4*j+1] = BETA_F * V1[4*j+1] + bb.y;
            V0[4*j+2] = BETA_F * V0[4*j+2] + bb.z;  V1[4*j+2] = BETA_F * V1[4*j+2] + bb.z;
            V0[4*j+3] = BETA_F * V0[4*j+3] + bb.w;  V1[4*j+3] = BETA_F * V1[4*j+3] + bb.w;
        }

        // conv: taps in ky,kx,ci ascending order (bit-identical to baseline)
#pragma unroll
        for (int ky = 0; ky < 3; ky++) {
            const int ra = (r0 + ky) * HALO_C + tx;       // pixel0 window row
            const int rb = ra + HALO_C;                    // pixel1 window row
            float2 a0, a1, a2, c0, c1, c2;
            a0.x = n2[ra+0].x - p2[ra+0].x;  a0.y = n2[ra+0].y - p2[ra+0].y;
            a1.x = n2[ra+1].x - p2[ra+1].x;  a1.y = n2[ra+1].y - p2[ra+1].y;
            a2.x = n2[ra+2].x - p2[ra+2].x;  a2.y = n2[ra+2].y - p2[ra+2].y;
            c0.x = n2[rb+0].x - p2[rb+0].x;  c0.y = n2[rb+0].y - p2[rb+0].y;
            c1.x = n2[rb+1].x - p2[rb+1].x;  c1.y = n2[rb+1].y - p2[rb+1].y;
            c2.x = n2[rb+2].x - p2[rb+2].x;  c2.y = n2[rb+2].y - p2[rb+2].y;
            const float2 A[3] = {a0, a1, a2};
            const float2 C[3] = {c0, c1, c2};
#pragma unroll
            for (int kx = 0; kx < 3; kx++) {
                const float fa0 = A[kx].x, fa1 = A[kx].y;   // pixel0, ci 0/1
                const float fc0 = C[kx].x, fc1 = C[kx].y;   // pixel1, ci 0/1
                const int tap0 = (ky * 3 + kx) * 2;
#pragma unroll
                for (int j = 0; j < 4; j++) {
                    float4 w = ws4[tap0 * 4 + j];
                    V0[4*j+0] += fa0 * w.x;  V1[4*j+0] += fc0 * w.x;
                    V0[4*j+1] += fa0 * w.y;  V1[4*j+1] += fc0 * w.y;
                    V0[4*j+2] += fa0 * w.z;  V1[4*j+2] += fc0 * w.z;
                    V0[4*j+3] += fa0 * w.w;  V1[4*j+3] += fc0 * w.w;
                }
#pragma unroll
                for (int j = 0; j < 4; j++) {
                    float4 w = ws4[(tap0 + 1) * 4 + j];
                    V0[4*j+0] += fa1 * w.x;  V1[4*j+0] += fc1 * w.x;
                    V0[4*j+1] += fa1 * w.y;  V1[4*j+1] += fc1 * w.y;
                    V0[4*j+2] += fa1 * w.z;  V1[4*j+2] += fc1 * w.z;
                    V0[4*j+3] += fa1 * w.w;  V1[4*j+3] += fc1 * w.w;
                }
            }
        }

        // spike + soft reset + warp-ballot counting (lane L<16 owns channel L)
        int acc = 0;
#pragma unroll
        for (int ch = 0; ch < QCH; ch++) {
            bool s0 = V0[ch] > THR_F;
            bool s1 = V1[ch] > THR_F;
            unsigned m0 = __ballot_sync(0xffffffffu, s0);
            unsigned m1 = __ballot_sync(0xffffffffu, s1);
            if (s0) V0[ch] -= THR_F;
            if (s1) V1[ch] -= THR_F;
            if (lane == ch) acc += __popc(m0) + __popc(m1);
        }
        if (lane < QCH) atomicAdd(&chsum_s[lane], acc);
    }

    // final flush (t = 18)
    __syncthreads();
    if (tid < QCH)
        atomicAdd(&g_chsum[((T_STEPS - 1) * BATCH + b) * NCH + q * QCH + tid],
                  chsum_s[tid]);
}

// ---------------------------------------------------------------------------
// Epilogue K1: grid 20. Blocks 0..18: logits for time t. Block 19: spike-rate.
// ---------------------------------------------------------------------------
__global__ void epilogue1_kernel(const float* __restrict__ w_head,
                                 const float* __restrict__ b_head,
                                 float* __restrict__ out) {
    const int t = blockIdx.x;
    const int tid = threadIdx.x;

    if (t < T_STEPS) {
        if (tid < BATCH * OUTD) {
            int b = tid / OUTD, o = tid % OUTD;
            const int* cs = g_chsum + (t * BATCH + b) * NCH;
            float acc = b_head[o];
            for (int ch = 0; ch < NCH; ch++)
                acc += ((float)cs[ch] * (1.0f / 16384.0f)) * w_head[ch * OUTD + o];
            out[160 + (t * BATCH + b) * OUTD + o] = acc;
        }
    } else {
        __shared__ long long part[256];
        long long tot = 0;
        for (int i = tid; i < T_STEPS * BATCH * NCH; i += 256)
            tot += (long long)g_chsum[i];
        part[tid] = tot;
        __syncthreads();
        for (int s = 128; s > 0; s >>= 1) {
            if (tid < s) part[tid] += part[tid + s];
            __syncthreads();
        }
        if (tid == 0)
            out[3200] = (float)((double)part[0] / 318767104.0);
    }
}

// ---------------------------------------------------------------------------
// Epilogue K2: readout = mean_t logits; re-zero g_chsum for next graph replay.
// ---------------------------------------------------------------------------
__global__ void epilogue2_kernel(float* __restrict__ out) {
    const int tid = threadIdx.x;
    if (tid < BATCH * OUTD) {
        int b = tid / OUTD, o = tid % OUTD;
        float s = 0.0f;
        for (int t = 0; t < T_STEPS; t++)
            s += out[160 + (t * BATCH + b) * OUTD + o];
        out[b * OUTD + o] = s * (1.0f / (float)T_STEPS);
    }
    for (int i = tid; i < T_STEPS * BATCH * NCH; i += 256) g_chsum[i] = 0;
}

// ---------------------------------------------------------------------------
extern "C" void kernel_launch(void* const* d_in, const int* in_sizes, int n_in,
                              void* d_out, int out_size) {
    const float* x     = (const float*)d_in[0];   // [20,16,128,128,2]
    const float* wconv = (const float*)d_in[1];   // [3,3,2,64]
    const float* bconv = (const float*)d_in[2];   // [64]
    const float* whead = (const float*)d_in[3];   // [64,10]
    const float* bhead = (const float*)d_in[4];   // [10]
    float* out = (float*)d_out;                   // 3201 floats

    lif_main_kernel<<<BATCH * 32 * 4, 256>>>(x, wconv, bconv);
    epilogue1_kernel<<<20, 256>>>(whead, bhead, out);
    epilogue2_kernel<<<1, 256>>>(out);
}